// round 8
// baseline (speedup 1.0000x reference)
#include <cuda_runtime.h>
#include <cuda_bf16.h>
#include <cstdint>

#define NMAX 100000
#define EMAX 640000
#define SLOT_CAP 64
#define PAD 40   // bf16 per smem row (32 data + 8 pad) -> 80B stride, conflict-free
#define ROWB 80  // bytes per smem row

// ---- persistent scratch ----
__device__ int g_is64;
__device__ int g_deg[NMAX];
__device__ int g_slot[(size_t)NMAX * SLOT_CAP];
__device__ __align__(16) float g_agg[(size_t)NMAX * 128];
__device__ __align__(16) float g_h1[(size_t)NMAX * 128];
// weights transposed to [n=128][k=256], bf16 hi/lo split
__device__ __align__(16) __nv_bfloat16 g_Bhw[2][128 * 256];
__device__ __align__(16) __nv_bfloat16 g_Blw[2][128 * 256];

// ---------------- helpers ----------------
__device__ __forceinline__ uint32_t smem_u32(const void* p) {
    uint32_t a;
    asm("{ .reg .u64 t; cvta.to.shared.u64 t, %1; cvt.u32.u64 %0, t; }" : "=r"(a) : "l"(p));
    return a;
}
__device__ __forceinline__ uint32_t packbf2(float lo, float hi) {
    __nv_bfloat162 t = __floats2bfloat162_rn(lo, hi);
    return *reinterpret_cast<uint32_t*>(&t);
}
__device__ __forceinline__ void mma_bf16(float* d, const uint32_t* a, const uint32_t* b) {
    asm volatile(
        "mma.sync.aligned.m16n8k16.row.col.f32.bf16.bf16.f32 "
        "{%0,%1,%2,%3}, {%4,%5,%6,%7}, {%8,%9}, {%0,%1,%2,%3};"
        : "+f"(d[0]), "+f"(d[1]), "+f"(d[2]), "+f"(d[3])
        : "r"(a[0]), "r"(a[1]), "r"(a[2]), "r"(a[3]), "r"(b[0]), "r"(b[1]));
}
__device__ __forceinline__ void ldmx4(uint32_t* r, uint32_t addr) {
    asm volatile("ldmatrix.sync.aligned.m8n8.x4.shared.b16 {%0,%1,%2,%3}, [%4];"
        : "=r"(r[0]), "=r"(r[1]), "=r"(r[2]), "=r"(r[3]) : "r"(addr));
}
__device__ __forceinline__ void cpasync16(uint32_t dst, const void* src) {
    asm volatile("cp.async.cg.shared.global [%0], [%1], 16;" :: "r"(dst), "l"(src));
}
#define CP_COMMIT() asm volatile("cp.async.commit_group;" ::: "memory")
#define CP_WAIT0()  asm volatile("cp.async.wait_group 0;" ::: "memory")

// ---------------- setup: weight prep + zero degrees + dtype probe ----------------
__global__ void k_setup(const int* __restrict__ a, int E, int N,
                        const float* __restrict__ W1l, const float* __restrict__ W1r,
                        const float* __restrict__ W2l, const float* __restrict__ W2r) {
    int i = blockIdx.x * 256 + threadIdx.x;
    if (i < 65536) {                      // prep both layers: transpose + bf16 hi/lo split
        int layer = i >> 15;
        int ii = i & 32767;
        int n = ii >> 8, k = ii & 255;
        const float* Wl = layer ? W2l : W1l;
        const float* Wr = layer ? W2r : W1r;
        float w = (k < 128) ? Wl[k * 128 + n] : Wr[(k - 128) * 128 + n];
        float h = __bfloat162float(__float2bfloat16(w));
        g_Bhw[layer][ii] = __float2bfloat16(h);
        g_Blw[layer][ii] = __float2bfloat16(w - h);
    }
    if (i < N) g_deg[i] = 0;
    if (blockIdx.x == 0) {                // dtype probe: int64 high words all zero?
        __shared__ int anynz;
        if (threadIdx.x == 0) anynz = 0;
        __syncthreads();
        int nz = 0;
#pragma unroll
        for (int r = 0; r < 8; r++) {
            int p = 2 * (threadIdx.x + r * 256) + 1;
            if (p < 2 * E && a[p] != 0) nz = 1;
        }
        if (nz) anynz = 1;
        __syncthreads();
        if (threadIdx.x == 0) g_is64 = anynz ? 0 : 1;
    }
}

__device__ __forceinline__ int ld_src(const int* a, int E, int e) {
    return g_is64 ? a[2 * e] : a[e];
}
__device__ __forceinline__ int ld_dst(const int* a, int E, int e) {
    return g_is64 ? a[2 * (E + e)] : a[E + e];
}

// ---------------- slot fill ----------------
__global__ void k_fill(const int* __restrict__ a, int E, int N) {
    int e = blockIdx.x * blockDim.x + threadIdx.x;
    if (e < E) {
        int s = ld_src(a, E, e);
        int d = ld_dst(a, E, e);
        if ((unsigned)d < (unsigned)N && (unsigned)s < (unsigned)N) {
            int p = atomicAdd(&g_deg[d], 1);
            if (p < SLOT_CAP) g_slot[(size_t)d * SLOT_CAP + p] = s;
        }
    }
}

// ---------------- mean aggregation: one warp per node, MLP=4 ----------------
__device__ __forceinline__ void add4(float4& a, const float4& v) {
    a.x += v.x; a.y += v.y; a.z += v.z; a.w += v.w;
}
__global__ void k_agg(const float* __restrict__ feat, int N, int useH1) {
    int w = (blockIdx.x * blockDim.x + threadIdx.x) >> 5;
    int lane = threadIdx.x & 31;
    if (w >= N) return;
    const float* f = useH1 ? (const float*)g_h1 : feat;
    int deg = g_deg[w];
    int cap = min(deg, SLOT_CAP);
    const int* sl = g_slot + (size_t)w * SLOT_CAP;
    float4 a0 = make_float4(0.f, 0.f, 0.f, 0.f), a1 = a0, a2 = a0, a3 = a0;
    int j = 0;
    for (; j + 4 <= cap; j += 4) {
        int i0 = sl[j], i1 = sl[j + 1], i2 = sl[j + 2], i3 = sl[j + 3];
        float4 v0 = ((const float4*)(f + (size_t)i0 * 128))[lane];
        float4 v1 = ((const float4*)(f + (size_t)i1 * 128))[lane];
        float4 v2 = ((const float4*)(f + (size_t)i2 * 128))[lane];
        float4 v3 = ((const float4*)(f + (size_t)i3 * 128))[lane];
        add4(a0, v0); add4(a1, v1); add4(a2, v2); add4(a3, v3);
    }
    for (; j < cap; j++)
        add4(a0, ((const float4*)(f + (size_t)sl[j] * 128))[lane]);
    add4(a0, a1); add4(a2, a3); add4(a0, a2);
    float inv = 1.0f / fmaxf((float)deg, 1.0f);
    a0.x *= inv; a0.y *= inv; a0.z *= inv; a0.w *= inv;
    ((float4*)(g_agg + (size_t)w * 128))[lane] = a0;
}

// ---------------- pipelined bf16-split tensor-core GEMM, dep-distance MMA order --------
// D[128,128] = [g_agg | A1](row0.., 256) @ W^T (g_Bhw/g_Blw [n][k], bf16 hi/lo).
// 3-product split: Ah*Bh + Ah*Bl + Al*Bh, issued product-major so consecutive
// MMAs never share an accumulator (RAW distance 4 instead of 1).
#define SM_A(b) ((uint32_t)(b) * 20480u)
#define SM_B(b) (40960u + (uint32_t)(b) * 20480u)
#define SM_BSM  81920u
#define SM_WLM  82432u
#define SM_RSUM 82944u
#define SMEM_REQ 83968

template <int FUSE>
__global__ void __launch_bounds__(256, 2) k_gemm_mma(
        const float* __restrict__ A1in, int layer,
        const float* __restrict__ bias,
        const float* __restrict__ Wlin, const float* __restrict__ blin,
        float* __restrict__ outS, int M) {
    extern __shared__ __align__(16) char dsm[];
    uint32_t su = smem_u32(dsm);
    float* bsm = (float*)(dsm + SM_BSM);
    float* wlm = (float*)(dsm + SM_WLM);
    float* rowsum = (float*)(dsm + SM_RSUM);

    int tid = threadIdx.x, lane = tid & 31, wid = tid >> 5;
    int wm = wid & 3, wn = wid >> 2;          // 4 warps M x 2 warps N
    int row0 = blockIdx.x * 128;
    const float* A1 = FUSE ? (const float*)g_h1 : A1in;
    const __nv_bfloat16* Bhw = g_Bhw[layer];
    const __nv_bfloat16* Blw = g_Blw[layer];

    if (tid < 128) { bsm[tid] = bias[tid]; rowsum[tid] = 0.f; }
    else if (FUSE) wlm[tid - 128] = Wlin[tid - 128];

    float acc[2][8][4];
#pragma unroll
    for (int i = 0; i < 2; i++)
#pragma unroll
        for (int j = 0; j < 8; j++)
#pragma unroll
            for (int t = 0; t < 4; t++) acc[i][j][t] = 0.f;

    // per-thread A staging coords
    int ar[4], aq[4];
#pragma unroll
    for (int it = 0; it < 4; it++) {
        int f = tid + it * 256;
        ar[it] = f >> 3;
        aq[it] = f & 7;
    }
    // per-thread B staging coords
    int br[2], bq[2];
#pragma unroll
    for (int it = 0; it < 2; it++) {
        int f = tid + it * 256;
        br[it] = f >> 2;
        bq[it] = f & 3;
    }

    auto storeA = [&](float4* vA, int b) {
        uint32_t AH = su + SM_A(b), AL = AH + 10240u;
#pragma unroll
        for (int it = 0; it < 4; it++) {
            float4 v = vA[it];
            float hx = __bfloat162float(__float2bfloat16(v.x));
            float hy = __bfloat162float(__float2bfloat16(v.y));
            float hz = __bfloat162float(__float2bfloat16(v.z));
            float hw = __bfloat162float(__float2bfloat16(v.w));
            uint32_t off = (uint32_t)(ar[it] * ROWB + aq[it] * 8);
            uint32_t h0 = packbf2(hx, hy), h1v = packbf2(hz, hw);
            uint32_t l0 = packbf2(v.x - hx, v.y - hy), l1v = packbf2(v.z - hz, v.w - hw);
            asm volatile("st.shared.v2.b32 [%0], {%1, %2};" :: "r"(AH + off), "r"(h0), "r"(h1v) : "memory");
            asm volatile("st.shared.v2.b32 [%0], {%1, %2};" :: "r"(AL + off), "r"(l0), "r"(l1v) : "memory");
        }
    };

    float4 vA[4];
    // ---- prologue: A0 -> regs -> buf0; B0 cp.async -> buf0
    {
#pragma unroll
        for (int it = 0; it < 2; it++) {
            uint32_t doff = (uint32_t)(br[it] * ROWB + bq[it] * 16);
            cpasync16(su + SM_B(0) + doff, Bhw + (size_t)br[it] * 256 + bq[it] * 8);
            cpasync16(su + SM_B(0) + 10240u + doff, Blw + (size_t)br[it] * 256 + bq[it] * 8);
        }
        CP_COMMIT();
#pragma unroll
        for (int it = 0; it < 4; it++) {
            int gr = row0 + ar[it];
            vA[it] = (gr < M) ? *(const float4*)(g_agg + (size_t)gr * 128 + aq[it] * 4)
                              : make_float4(0.f, 0.f, 0.f, 0.f);
        }
        storeA(vA, 0);
    }

    for (int c = 0; c < 8; c++) {
        int buf = c & 1;
        CP_WAIT0();          // B(c) resident
        __syncthreads();     // A(c) stores visible; prior readers of buf^1 done

        // ---- prefetch chunk c+1 into buf^1 (overlaps compute below)
        if (c < 7) {
            int cc = c + 1;
            int kfull = cc * 32;
            uint32_t bb = su + SM_B(buf ^ 1);
#pragma unroll
            for (int it = 0; it < 2; it++) {
                uint32_t doff = (uint32_t)(br[it] * ROWB + bq[it] * 16);
                cpasync16(bb + doff, Bhw + (size_t)br[it] * 256 + kfull + bq[it] * 8);
                cpasync16(bb + 10240u + doff, Blw + (size_t)br[it] * 256 + kfull + bq[it] * 8);
            }
            CP_COMMIT();
            const float* Asrc = (cc < 4) ? (const float*)g_agg : A1;
            int kb = (cc & 3) * 32;
#pragma unroll
            for (int it = 0; it < 4; it++) {
                int gr = row0 + ar[it];
                vA[it] = (gr < M) ? *(const float4*)(Asrc + (size_t)gr * 128 + kb + aq[it] * 4)
                                  : make_float4(0.f, 0.f, 0.f, 0.f);
            }
        }

        // ---- compute chunk c
        uint32_t AHu = su + SM_A(buf), ALu = AHu + 10240u;
        uint32_t BHu = su + SM_B(buf), BLu = BHu + 10240u;
#pragma unroll
        for (int ks = 0; ks < 32; ks += 16) {
            uint32_t ah[2][4], al[2][4];
            int arow = lane & 15;
            int acol = ks * 2 + (lane & 16);      // byte offset within row
#pragma unroll
            for (int i = 0; i < 2; i++) {
                uint32_t ro = (uint32_t)((wm * 32 + i * 16 + arow) * ROWB + acol);
                ldmx4(ah[i], AHu + ro);
                ldmx4(al[i], ALu + ro);
            }
            int brow = (lane & 7) + ((lane & 16) >> 1);
            int bcol = ks * 2 + ((lane & 8) << 1);
#pragma unroll
            for (int jp = 0; jp < 4; jp++) {
                int n0 = wn * 64 + jp * 16;
                uint32_t ro = (uint32_t)((n0 + brow) * ROWB + bcol);
                uint32_t bh[4], bl[4];
                ldmx4(bh, BHu + ro);
                ldmx4(bl, BLu + ro);
                // product-major issue order: consecutive MMAs hit distinct
                // accumulators; same-acc RAW distance = 4 issue slots.
#pragma unroll
                for (int i = 0; i < 2; i++) {
                    mma_bf16(acc[i][2 * jp],     ah[i], bh);
                    mma_bf16(acc[i][2 * jp + 1], ah[i], bh + 2);
                }
#pragma unroll
                for (int i = 0; i < 2; i++) {
                    mma_bf16(acc[i][2 * jp],     ah[i], bl);
                    mma_bf16(acc[i][2 * jp + 1], ah[i], bl + 2);
                }
#pragma unroll
                for (int i = 0; i < 2; i++) {
                    mma_bf16(acc[i][2 * jp],     al[i], bh);
                    mma_bf16(acc[i][2 * jp + 1], al[i], bh + 2);
                }
            }
        }
        // ---- stage A(c+1) into buf^1
        if (c < 7) storeA(vA, buf ^ 1);
    }

    int g = lane >> 2, q = lane & 3;
    // ---- epilogue ----
    if (FUSE) {
#pragma unroll
        for (int i = 0; i < 2; i++) {
            float pg = 0.f, pg8 = 0.f;
#pragma unroll
            for (int j = 0; j < 8; j++) {
                int cb = wn * 64 + j * 8 + 2 * q;
                float y;
                y = fmaxf(acc[i][j][0] + bsm[cb],     0.f); pg  = fmaf(y, wlm[cb],     pg);
                y = fmaxf(acc[i][j][1] + bsm[cb + 1], 0.f); pg  = fmaf(y, wlm[cb + 1], pg);
                y = fmaxf(acc[i][j][2] + bsm[cb],     0.f); pg8 = fmaf(y, wlm[cb],     pg8);
                y = fmaxf(acc[i][j][3] + bsm[cb + 1], 0.f); pg8 = fmaf(y, wlm[cb + 1], pg8);
            }
            pg  += __shfl_xor_sync(0xffffffffu, pg, 1);
            pg  += __shfl_xor_sync(0xffffffffu, pg, 2);
            pg8 += __shfl_xor_sync(0xffffffffu, pg8, 1);
            pg8 += __shfl_xor_sync(0xffffffffu, pg8, 2);
            if (q == 0) {
                atomicAdd(&rowsum[wm * 32 + i * 16 + g], pg);
                atomicAdd(&rowsum[wm * 32 + i * 16 + g + 8], pg8);
            }
        }
        __syncthreads();
        if (tid < 128 && row0 + tid < M) outS[row0 + tid] = rowsum[tid] + blin[0];
    } else {
#pragma unroll
        for (int i = 0; i < 2; i++) {
            int r1 = row0 + wm * 32 + i * 16 + g;
            int r2 = r1 + 8;
#pragma unroll
            for (int j = 0; j < 8; j++) {
                int cb = wn * 64 + j * 8 + 2 * q;
                if (r1 < M) {
                    float2 o;
                    o.x = fmaxf(acc[i][j][0] + bsm[cb],     0.f);
                    o.y = fmaxf(acc[i][j][1] + bsm[cb + 1], 0.f);
                    *(float2*)(g_h1 + (size_t)r1 * 128 + cb) = o;
                }
                if (r2 < M) {
                    float2 o;
                    o.x = fmaxf(acc[i][j][2] + bsm[cb],     0.f);
                    o.y = fmaxf(acc[i][j][3] + bsm[cb + 1], 0.f);
                    *(float2*)(g_h1 + (size_t)r2 * 128 + cb) = o;
                }
            }
        }
    }
}

extern "C" void kernel_launch(void* const* d_in, const int* in_sizes, int n_in,
                              void* d_out, int out_size) {
    const float* x    = (const float*)d_in[0];
    const int*   ei   = (const int*)d_in[1];   // int32 or int64 (device probe)
    const float* W1l  = (const float*)d_in[2];
    const float* b1   = (const float*)d_in[3];
    const float* W1r  = (const float*)d_in[4];
    const float* W2l  = (const float*)d_in[5];
    const float* b2   = (const float*)d_in[6];
    const float* W2r  = (const float*)d_in[7];
    const float* Wlin = (const float*)d_in[8];
    const float* blin = (const float*)d_in[9];
    float* out = (float*)d_out;

    int N = in_sizes[0] / 128;
    int E = in_sizes[1] / 2;
    if (N > NMAX) N = NMAX;
    if (E > EMAX) E = EMAX;

    cudaFuncSetAttribute(k_gemm_mma<0>, cudaFuncAttributeMaxDynamicSharedMemorySize, SMEM_REQ);
    cudaFuncSetAttribute(k_gemm_mma<1>, cudaFuncAttributeMaxDynamicSharedMemorySize, SMEM_REQ);

    int aggBlocks = (int)(((long long)N * 32 + 255) / 256);
    int gb = (N + 127) / 128;
    int sb = (N + 255) / 256;
    if (sb < 256) sb = 256;

    k_setup<<<sb, 256>>>(ei, E, N, W1l, W1r, W2l, W2r);                       // 0
    k_fill<<<(E + 255) / 256, 256>>>(ei, E, N);                               // 1
    k_agg<<<aggBlocks, 256>>>(x, N, 0);                                       // 2
    k_gemm_mma<0><<<gb, 256, SMEM_REQ>>>(x, 0, b1, nullptr, nullptr, nullptr, N);  // 3 (profiled)
    k_agg<<<aggBlocks, 256>>>(nullptr, N, 1);                                 // 4
    k_gemm_mma<1><<<gb, 256, SMEM_REQ>>>(nullptr, 1, b2, Wlin, blin, out, N); // 5
}

// round 9
// speedup vs baseline: 1.0059x; 1.0059x over previous
#include <cuda_runtime.h>
#include <cuda_bf16.h>
#include <cstdint>

#define NMAX 100000
#define EMAX 640000
#define SLOT_CAP 64
#define PAD 40   // bf16 per smem row (32 data + 8 pad) -> 80B stride, conflict-free
#define ROWB 80  // bytes per smem row

// ---- persistent scratch ----
__device__ int g_is64;
__device__ int g_deg[NMAX];
__device__ int g_slot[(size_t)NMAX * SLOT_CAP];
__device__ __align__(16) float g_agg[(size_t)NMAX * 128];
__device__ __align__(16) float g_h1[(size_t)NMAX * 128];
// weights transposed to [n=128][k=256], bf16 hi/lo split
__device__ __align__(16) __nv_bfloat16 g_Bhw[2][128 * 256];
__device__ __align__(16) __nv_bfloat16 g_Blw[2][128 * 256];

// ---------------- helpers ----------------
__device__ __forceinline__ uint32_t smem_u32(const void* p) {
    uint32_t a;
    asm("{ .reg .u64 t; cvta.to.shared.u64 t, %1; cvt.u32.u64 %0, t; }" : "=r"(a) : "l"(p));
    return a;
}
__device__ __forceinline__ uint32_t packbf2(float lo, float hi) {
    __nv_bfloat162 t = __floats2bfloat162_rn(lo, hi);
    return *reinterpret_cast<uint32_t*>(&t);
}
__device__ __forceinline__ void mma_bf16(float* d, const uint32_t* a, const uint32_t* b) {
    asm volatile(
        "mma.sync.aligned.m16n8k16.row.col.f32.bf16.bf16.f32 "
        "{%0,%1,%2,%3}, {%4,%5,%6,%7}, {%8,%9}, {%0,%1,%2,%3};"
        : "+f"(d[0]), "+f"(d[1]), "+f"(d[2]), "+f"(d[3])
        : "r"(a[0]), "r"(a[1]), "r"(a[2]), "r"(a[3]), "r"(b[0]), "r"(b[1]));
}
__device__ __forceinline__ void ldmx4(uint32_t* r, uint32_t addr) {
    asm volatile("ldmatrix.sync.aligned.m8n8.x4.shared.b16 {%0,%1,%2,%3}, [%4];"
        : "=r"(r[0]), "=r"(r[1]), "=r"(r[2]), "=r"(r[3]) : "r"(addr));
}
__device__ __forceinline__ void cpasync16(uint32_t dst, const void* src) {
    asm volatile("cp.async.cg.shared.global [%0], [%1], 16;" :: "r"(dst), "l"(src));
}
#define CP_COMMIT() asm volatile("cp.async.commit_group;" ::: "memory")
#define CP_WAIT0()  asm volatile("cp.async.wait_group 0;" ::: "memory")

// ---------------- setup: weight prep + zero degrees + dtype probe ----------------
__global__ void k_setup(const int* __restrict__ a, int E, int N,
                        const float* __restrict__ W1l, const float* __restrict__ W1r,
                        const float* __restrict__ W2l, const float* __restrict__ W2r) {
    int i = blockIdx.x * 256 + threadIdx.x;
    if (i < 65536) {                      // prep both layers: transpose + bf16 hi/lo split
        int layer = i >> 15;
        int ii = i & 32767;
        int n = ii >> 8, k = ii & 255;
        const float* Wl = layer ? W2l : W1l;
        const float* Wr = layer ? W2r : W1r;
        float w = (k < 128) ? Wl[k * 128 + n] : Wr[(k - 128) * 128 + n];
        float h = __bfloat162float(__float2bfloat16(w));
        g_Bhw[layer][ii] = __float2bfloat16(h);
        g_Blw[layer][ii] = __float2bfloat16(w - h);
    }
    if (i < N) g_deg[i] = 0;
    if (blockIdx.x == 0) {                // dtype probe: int64 high words all zero?
        __shared__ int anynz;
        if (threadIdx.x == 0) anynz = 0;
        __syncthreads();
        int nz = 0;
#pragma unroll
        for (int r = 0; r < 8; r++) {
            int p = 2 * (threadIdx.x + r * 256) + 1;
            if (p < 2 * E && a[p] != 0) nz = 1;
        }
        if (nz) anynz = 1;
        __syncthreads();
        if (threadIdx.x == 0) g_is64 = anynz ? 0 : 1;
    }
}

__device__ __forceinline__ int ld_src(const int* a, int E, int e) {
    return g_is64 ? a[2 * e] : a[e];
}
__device__ __forceinline__ int ld_dst(const int* a, int E, int e) {
    return g_is64 ? a[2 * (E + e)] : a[E + e];
}

// ---------------- slot fill ----------------
__global__ void k_fill(const int* __restrict__ a, int E, int N) {
    int e = blockIdx.x * blockDim.x + threadIdx.x;
    if (e < E) {
        int s = ld_src(a, E, e);
        int d = ld_dst(a, E, e);
        if ((unsigned)d < (unsigned)N && (unsigned)s < (unsigned)N) {
            int p = atomicAdd(&g_deg[d], 1);
            if (p < SLOT_CAP) g_slot[(size_t)d * SLOT_CAP + p] = s;
        }
    }
}

// ---------------- mean aggregation: one warp per node, MLP=4 ----------------
__device__ __forceinline__ void add4(float4& a, const float4& v) {
    a.x += v.x; a.y += v.y; a.z += v.z; a.w += v.w;
}
__global__ void k_agg(const float* __restrict__ feat, int N, int useH1) {
    int w = (blockIdx.x * blockDim.x + threadIdx.x) >> 5;
    int lane = threadIdx.x & 31;
    if (w >= N) return;
    const float* f = useH1 ? (const float*)g_h1 : feat;
    int deg = g_deg[w];
    int cap = min(deg, SLOT_CAP);
    const int* sl = g_slot + (size_t)w * SLOT_CAP;
    float4 a0 = make_float4(0.f, 0.f, 0.f, 0.f), a1 = a0, a2 = a0, a3 = a0;
    int j = 0;
    for (; j + 4 <= cap; j += 4) {
        int i0 = sl[j], i1 = sl[j + 1], i2 = sl[j + 2], i3 = sl[j + 3];
        float4 v0 = ((const float4*)(f + (size_t)i0 * 128))[lane];
        float4 v1 = ((const float4*)(f + (size_t)i1 * 128))[lane];
        float4 v2 = ((const float4*)(f + (size_t)i2 * 128))[lane];
        float4 v3 = ((const float4*)(f + (size_t)i3 * 128))[lane];
        add4(a0, v0); add4(a1, v1); add4(a2, v2); add4(a3, v3);
    }
    for (; j < cap; j++)
        add4(a0, ((const float4*)(f + (size_t)sl[j] * 128))[lane]);
    add4(a0, a1); add4(a2, a3); add4(a0, a2);
    float inv = 1.0f / fmaxf((float)deg, 1.0f);
    a0.x *= inv; a0.y *= inv; a0.z *= inv; a0.w *= inv;
    ((float4*)(g_agg + (size_t)w * 128))[lane] = a0;
}

// ---------------- pipelined bf16-split tensor-core GEMM, 64x128 tile, 3 CTAs/SM ----
// D[64,128] = [g_agg | A1](row0.., 256) @ W^T (g_Bhw/g_Blw [n][k], bf16 hi/lo).
// 3-product split: Ah*Bh + Ah*Bl + Al*Bh. 8 warps as 2(M) x 4(N), warp tile 32x32.
// Dyn SMEM (bytes): A buf b at b*10240 (Ah +0, Al +5120);
//   B buf b at 20480 + b*20480 (Bh +0, Bl +10240);
//   BSM 61440, WLM 61952, RSUM 62464(64f); total req 62976.
#define SM_A(b) ((uint32_t)(b) * 10240u)
#define SM_B(b) (20480u + (uint32_t)(b) * 20480u)
#define SM_BSM  61440u
#define SM_WLM  61952u
#define SM_RSUM 62464u
#define SMEM_REQ 62976

template <int FUSE>
__global__ void __launch_bounds__(256, 3) k_gemm_mma(
        const float* __restrict__ A1in, int layer,
        const float* __restrict__ bias,
        const float* __restrict__ Wlin, const float* __restrict__ blin,
        float* __restrict__ outS, int M) {
    extern __shared__ __align__(16) char dsm[];
    uint32_t su = smem_u32(dsm);
    float* bsm = (float*)(dsm + SM_BSM);
    float* wlm = (float*)(dsm + SM_WLM);
    float* rowsum = (float*)(dsm + SM_RSUM);

    int tid = threadIdx.x, lane = tid & 31, wid = tid >> 5;
    int wm = wid & 1, wn = wid >> 1;          // 2 warps M x 4 warps N
    int row0 = blockIdx.x * 64;
    const float* A1 = FUSE ? (const float*)g_h1 : A1in;
    const __nv_bfloat16* Bhw = g_Bhw[layer];
    const __nv_bfloat16* Blw = g_Blw[layer];

    if (tid < 128) bsm[tid] = bias[tid];
    else if (FUSE) wlm[tid - 128] = Wlin[tid - 128];
    if (tid < 64) rowsum[tid] = 0.f;

    float acc[2][4][4];
#pragma unroll
    for (int i = 0; i < 2; i++)
#pragma unroll
        for (int j = 0; j < 4; j++)
#pragma unroll
            for (int t = 0; t < 4; t++) acc[i][j][t] = 0.f;

    // per-thread A staging coords: 64 rows x 8 quads = 512 float4 slots / 256 thr
    int ar[2], aq[2];
#pragma unroll
    for (int it = 0; it < 2; it++) {
        int f = tid + it * 256;
        ar[it] = f >> 3;          // 0..63
        aq[it] = f & 7;
    }
    // per-thread B staging coords (128 n-rows x 4 uint4)
    int br[2], bq[2];
#pragma unroll
    for (int it = 0; it < 2; it++) {
        int f = tid + it * 256;
        br[it] = f >> 2;
        bq[it] = f & 3;
    }

    auto storeA = [&](float4* vA, int b) {
        uint32_t AH = su + SM_A(b), AL = AH + 5120u;
#pragma unroll
        for (int it = 0; it < 2; it++) {
            float4 v = vA[it];
            float hx = __bfloat162float(__float2bfloat16(v.x));
            float hy = __bfloat162float(__float2bfloat16(v.y));
            float hz = __bfloat162float(__float2bfloat16(v.z));
            float hw = __bfloat162float(__float2bfloat16(v.w));
            uint32_t off = (uint32_t)(ar[it] * ROWB + aq[it] * 8);
            uint32_t h0 = packbf2(hx, hy), h1v = packbf2(hz, hw);
            uint32_t l0 = packbf2(v.x - hx, v.y - hy), l1v = packbf2(v.z - hz, v.w - hw);
            asm volatile("st.shared.v2.b32 [%0], {%1, %2};" :: "r"(AH + off), "r"(h0), "r"(h1v) : "memory");
            asm volatile("st.shared.v2.b32 [%0], {%1, %2};" :: "r"(AL + off), "r"(l0), "r"(l1v) : "memory");
        }
    };

    float4 vA[2];
    // ---- prologue: A0 -> regs -> buf0; B0 cp.async -> buf0
    {
#pragma unroll
        for (int it = 0; it < 2; it++) {
            uint32_t doff = (uint32_t)(br[it] * ROWB + bq[it] * 16);
            cpasync16(su + SM_B(0) + doff, Bhw + (size_t)br[it] * 256 + bq[it] * 8);
            cpasync16(su + SM_B(0) + 10240u + doff, Blw + (size_t)br[it] * 256 + bq[it] * 8);
        }
        CP_COMMIT();
#pragma unroll
        for (int it = 0; it < 2; it++) {
            int gr = row0 + ar[it];
            vA[it] = (gr < M) ? *(const float4*)(g_agg + (size_t)gr * 128 + aq[it] * 4)
                              : make_float4(0.f, 0.f, 0.f, 0.f);
        }
        storeA(vA, 0);
    }

    for (int c = 0; c < 8; c++) {
        int buf = c & 1;
        CP_WAIT0();          // B(c) resident
        __syncthreads();     // A(c) stores visible; prior readers of buf^1 done

        // ---- prefetch chunk c+1 into buf^1 (overlaps compute below)
        if (c < 7) {
            int cc = c + 1;
            int kfull = cc * 32;
            uint32_t bb = su + SM_B(buf ^ 1);
#pragma unroll
            for (int it = 0; it < 2; it++) {
                uint32_t doff = (uint32_t)(br[it] * ROWB + bq[it] * 16);
                cpasync16(bb + doff, Bhw + (size_t)br[it] * 256 + kfull + bq[it] * 8);
                cpasync16(bb + 10240u + doff, Blw + (size_t)br[it] * 256 + kfull + bq[it] * 8);
            }
            CP_COMMIT();
            const float* Asrc = (cc < 4) ? (const float*)g_agg : A1;
            int kb = (cc & 3) * 32;
#pragma unroll
            for (int it = 0; it < 2; it++) {
                int gr = row0 + ar[it];
                vA[it] = (gr < M) ? *(const float4*)(Asrc + (size_t)gr * 128 + kb + aq[it] * 4)
                                  : make_float4(0.f, 0.f, 0.f, 0.f);
            }
        }

        // ---- compute chunk c
        uint32_t AHu = su + SM_A(buf), ALu = AHu + 5120u;
        uint32_t BHu = su + SM_B(buf), BLu = BHu + 10240u;
#pragma unroll
        for (int ks = 0; ks < 32; ks += 16) {
            uint32_t ah[2][4], al[2][4];
            int arow = lane & 15;
            int acol = ks * 2 + (lane & 16);      // byte offset within row
#pragma unroll
            for (int i = 0; i < 2; i++) {
                uint32_t ro = (uint32_t)((wm * 32 + i * 16 + arow) * ROWB + acol);
                ldmx4(ah[i], AHu + ro);
                ldmx4(al[i], ALu + ro);
            }
            int brow = (lane & 7) + ((lane & 16) >> 1);
            int bcol = ks * 2 + ((lane & 8) << 1);
#pragma unroll
            for (int jp = 0; jp < 2; jp++) {
                int n0 = wn * 32 + jp * 16;
                uint32_t ro = (uint32_t)((n0 + brow) * ROWB + bcol);
                uint32_t bh[4], bl[4];
                ldmx4(bh, BHu + ro);
                ldmx4(bl, BLu + ro);
                // product-major: consecutive MMAs hit distinct accumulators
#pragma unroll
                for (int i = 0; i < 2; i++) {
                    mma_bf16(acc[i][2 * jp],     ah[i], bh);
                    mma_bf16(acc[i][2 * jp + 1], ah[i], bh + 2);
                }
#pragma unroll
                for (int i = 0; i < 2; i++) {
                    mma_bf16(acc[i][2 * jp],     ah[i], bl);
                    mma_bf16(acc[i][2 * jp + 1], ah[i], bl + 2);
                }
#pragma unroll
                for (int i = 0; i < 2; i++) {
                    mma_bf16(acc[i][2 * jp],     al[i], bh);
                    mma_bf16(acc[i][2 * jp + 1], al[i], bh + 2);
                }
            }
        }
        // ---- stage A(c+1) into buf^1
        if (c < 7) storeA(vA, buf ^ 1);
    }

    int g = lane >> 2, q = lane & 3;
    // ---- epilogue ----
    if (FUSE) {
#pragma unroll
        for (int i = 0; i < 2; i++) {
            float pg = 0.f, pg8 = 0.f;
#pragma unroll
            for (int j = 0; j < 4; j++) {
                int cb = wn * 32 + j * 8 + 2 * q;
                float y;
                y = fmaxf(acc[i][j][0] + bsm[cb],     0.f); pg  = fmaf(y, wlm[cb],     pg);
                y = fmaxf(acc[i][j][1] + bsm[cb + 1], 0.f); pg  = fmaf(y, wlm[cb + 1], pg);
                y = fmaxf(acc[i][j][2] + bsm[cb],     0.f); pg8 = fmaf(y, wlm[cb],     pg8);
                y = fmaxf(acc[i][j][3] + bsm[cb + 1], 0.f); pg8 = fmaf(y, wlm[cb + 1], pg8);
            }
            pg  += __shfl_xor_sync(0xffffffffu, pg, 1);
            pg  += __shfl_xor_sync(0xffffffffu, pg, 2);
            pg8 += __shfl_xor_sync(0xffffffffu, pg8, 1);
            pg8 += __shfl_xor_sync(0xffffffffu, pg8, 2);
            if (q == 0) {
                atomicAdd(&rowsum[wm * 32 + i * 16 + g], pg);
                atomicAdd(&rowsum[wm * 32 + i * 16 + g + 8], pg8);
            }
        }
        __syncthreads();
        if (tid < 64 && row0 + tid < M) outS[row0 + tid] = rowsum[tid] + blin[0];
    } else {
#pragma unroll
        for (int i = 0; i < 2; i++) {
            int r1 = row0 + wm * 32 + i * 16 + g;
            int r2 = r1 + 8;
#pragma unroll
            for (int j = 0; j < 4; j++) {
                int cb = wn * 32 + j * 8 + 2 * q;
                if (r1 < M) {
                    float2 o;
                    o.x = fmaxf(acc[i][j][0] + bsm[cb],     0.f);
                    o.y = fmaxf(acc[i][j][1] + bsm[cb + 1], 0.f);
                    *(float2*)(g_h1 + (size_t)r1 * 128 + cb) = o;
                }
                if (r2 < M) {
                    float2 o;
                    o.x = fmaxf(acc[i][j][2] + bsm[cb],     0.f);
                    o.y = fmaxf(acc[i][j][3] + bsm[cb + 1], 0.f);
                    *(float2*)(g_h1 + (size_t)r2 * 128 + cb) = o;
                }
            }
        }
    }
}

extern "C" void kernel_launch(void* const* d_in, const int* in_sizes, int n_in,
                              void* d_out, int out_size) {
    const float* x    = (const float*)d_in[0];
    const int*   ei   = (const int*)d_in[1];   // int32 or int64 (device probe)
    const float* W1l  = (const float*)d_in[2];
    const float* b1   = (const float*)d_in[3];
    const float* W1r  = (const float*)d_in[4];
    const float* W2l  = (const float*)d_in[5];
    const float* b2   = (const float*)d_in[6];
    const float* W2r  = (const float*)d_in[7];
    const float* Wlin = (const float*)d_in[8];
    const float* blin = (const float*)d_in[9];
    float* out = (float*)d_out;

    int N = in_sizes[0] / 128;
    int E = in_sizes[1] / 2;
    if (N > NMAX) N = NMAX;
    if (E > EMAX) E = EMAX;

    cudaFuncSetAttribute(k_gemm_mma<0>, cudaFuncAttributeMaxDynamicSharedMemorySize, SMEM_REQ);
    cudaFuncSetAttribute(k_gemm_mma<1>, cudaFuncAttributeMaxDynamicSharedMemorySize, SMEM_REQ);

    int aggBlocks = (int)(((long long)N * 32 + 255) / 256);
    int gb = (N + 63) / 64;
    int sb = (N + 255) / 256;
    if (sb < 256) sb = 256;

    k_setup<<<sb, 256>>>(ei, E, N, W1l, W1r, W2l, W2r);                       // 0
    k_fill<<<(E + 255) / 256, 256>>>(ei, E, N);                               // 1
    k_agg<<<aggBlocks, 256>>>(x, N, 0);                                       // 2
    k_gemm_mma<0><<<gb, 256, SMEM_REQ>>>(x, 0, b1, nullptr, nullptr, nullptr, N);  // 3 (profiled)
    k_agg<<<aggBlocks, 256>>>(nullptr, N, 1);                                 // 4
    k_gemm_mma<1><<<gb, 256, SMEM_REQ>>>(nullptr, 1, b2, Wlin, blin, out, N); // 5
}